// round 3
// baseline (speedup 1.0000x reference)
#include <cuda_runtime.h>
#include <cstdint>

#define B_TOT   32768
#define SAMP    16
#define D       256
#define NREL    238
#define BM      64
#define KC      32
#define NTHREADS 256

// ---------------- scratch (device globals: only legal scratch) ----------------
__device__ float g_Wt[D * D];             // Wt[d*256 + do] = W[do*256 + d]
__device__ float g_relinit[B_TOT * D];    // per-row relation means

// ---------------- packed fp32x2 helpers ----------------
__device__ __forceinline__ void fma2(unsigned long long& c, unsigned long long a,
                                     unsigned long long b) {
    asm("fma.rn.f32x2 %0, %1, %2, %0;" : "+l"(c) : "l"(a), "l"(b));
}
__device__ __forceinline__ unsigned long long splat2(float x) {
    unsigned long long r;
    asm("mov.b64 %0, {%1, %1};" : "=l"(r) : "f"(x));
    return r;
}
__device__ __forceinline__ float2 unpack2(unsigned long long v) {
    float2 f;
    asm("mov.b64 {%0, %1}, %2;" : "=f"(f.x), "=f"(f.y) : "l"(v));
    return f;
}

// ---------------- kernel 1: transpose weight [256,256] -> g_Wt ----------------
__global__ void k_wt(const float* __restrict__ W) {
    int idx = blockIdx.x * 256 + threadIdx.x;   // 65536 elems, grid = 256
    int dout = idx >> 8;
    int d    = idx & 255;
    g_Wt[d * D + dout] = W[idx];                // coalesced read, scattered write (tiny)
}

// ---------------- kernel 2: relation means, relT resident in SMEM (fp32, 2 passes) ----
__global__ __launch_bounds__(256, 1) void k_rel(const int* __restrict__ rel,
                                                const float* __restrict__ rw) {
    extern __shared__ float sT[];               // [NREL][129] padded (one d-half)
    const int tid    = threadIdx.x;
    const int bstart = blockIdx.x * 128;        // grid = 256 blocks, 128 rows each

    for (int p = 0; p < 2; ++p) {
        __syncthreads();                        // previous pass readers done
        // stage relation_weight[:, :] transposed for d in [128p, 128p+128)
        // rw layout [256][238]; linear idx over (dloc, r) is a coalesced read.
        for (int idx = tid; idx < NREL * 128; idx += 256) {
            int dloc = idx / NREL;
            int r    = idx - dloc * NREL;
            sT[r * 129 + dloc] = rw[p * 128 * NREL + idx];
        }
        __syncthreads();

        const int d  = tid & 127;
        const int bh = tid >> 7;
        for (int k = 0; k < 64; ++k) {
            int b = bstart + 2 * k + bh;
            const int* rb = rel + b * SAMP;
            float acc = 0.f;
            #pragma unroll
            for (int s = 0; s < SAMP; ++s) {
                int r = __ldg(rb + s);          // warp-uniform -> broadcast
                acc += sT[r * 129 + d];         // lanes consecutive d: conflict-free
            }
            g_relinit[b * D + p * 128 + d] = acc * (1.f / 16.f);
        }
    }
}

// ---------------- kernel 3: fused gather-mean + GEMM + rel-add + relu ----------------
__global__ __launch_bounds__(NTHREADS, 2) void k_main(const int* __restrict__ nbr,
                                                      const float* __restrict__ feat,
                                                      float* __restrict__ out) {
    extern __shared__ float smem[];
    float* sAgg = smem;                         // [64][256]  (65536 B)
    float* sW   = smem + BM * D;                // [KC][256]  (32768 B)
    int*   sIdx = (int*)(smem + BM * D + KC * D);  // 1024 ints (4096 B)

    const int tid = threadIdx.x;
    const int b0  = blockIdx.x * BM;

    // stage neighbor indices (contiguous 1024 ints)
    ((int4*)sIdx)[tid] = ((const int4*)(nbr + b0 * SAMP))[tid];
    __syncthreads();

    // ---------- Phase A: gather + mean into sAgg ----------
    {
        const int q  = tid & 63;                // float4 column within 256-dim row
        const int bg = tid >> 6;                // 0..3
        const float4* F4 = (const float4*)feat;
        #pragma unroll 2
        for (int k = 0; k < 16; ++k) {
            const int b = bg * 16 + k;          // warp-uniform b -> broadcast idx loads
            const int* ids = sIdx + b * SAMP;
            float4 acc = make_float4(0.f, 0.f, 0.f, 0.f);
            #pragma unroll
            for (int s = 0; s < SAMP; ++s) {
                int n = ids[s];
                float4 v = F4[n * 64 + q];      // warp reads 512B contiguous
                acc.x += v.x; acc.y += v.y; acc.z += v.z; acc.w += v.w;
            }
            const float inv = 1.f / 16.f;
            acc.x *= inv; acc.y *= inv; acc.z *= inv; acc.w *= inv;
            *(float4*)&sAgg[b * D + q * 4] = acc;
        }
    }
    __syncthreads();

    // ---------- Phase B: GEMM out[64][256] = sAgg @ W^T, packed f32x2 ----------
    const int lane = tid & 31;
    const int warp = tid >> 5;
    const int row0 = warp * 8;                  // 8 rows per warp

    unsigned long long acc[8][4];               // 8 rows x 8 cols (cols 4*lane.. and +128)
    #pragma unroll
    for (int i = 0; i < 8; ++i)
        #pragma unroll
        for (int j = 0; j < 4; ++j) acc[i][j] = 0ull;

    for (int kc = 0; kc < D; kc += KC) {
        __syncthreads();
        // stage weight chunk: g_Wt rows [kc, kc+KC) are a contiguous 32KB block
        {
            const float4* src = (const float4*)(g_Wt + kc * D);
            float4* dst = (float4*)sW;
            #pragma unroll
            for (int i = 0; i < (KC * D / 4) / NTHREADS; ++i)   // 8 iters
                dst[tid + i * NTHREADS] = src[tid + i * NTHREADS];
        }
        __syncthreads();

        for (int dd = 0; dd < KC; dd += 2) {
            float2 av[8];
            #pragma unroll
            for (int i = 0; i < 8; ++i)         // broadcast LDS.64 (d, d+1)
                av[i] = *(const float2*)&sAgg[(row0 + i) * D + kc + dd];

            ulonglong2 b00 = *(const ulonglong2*)&sW[dd * D + 4 * lane];
            ulonglong2 b01 = *(const ulonglong2*)&sW[dd * D + 128 + 4 * lane];
            ulonglong2 b10 = *(const ulonglong2*)&sW[(dd + 1) * D + 4 * lane];
            ulonglong2 b11 = *(const ulonglong2*)&sW[(dd + 1) * D + 128 + 4 * lane];

            #pragma unroll
            for (int i = 0; i < 8; ++i) {
                unsigned long long ax = splat2(av[i].x);
                fma2(acc[i][0], ax, b00.x);
                fma2(acc[i][1], ax, b00.y);
                fma2(acc[i][2], ax, b01.x);
                fma2(acc[i][3], ax, b01.y);
                unsigned long long ay = splat2(av[i].y);
                fma2(acc[i][0], ay, b10.x);
                fma2(acc[i][1], ay, b10.y);
                fma2(acc[i][2], ay, b11.x);
                fma2(acc[i][3], ay, b11.y);
            }
        }
    }

    // ---------- Epilogue: + relation mean, relu, store ----------
    const int c0 = 4 * lane;
    #pragma unroll
    for (int i = 0; i < 8; ++i) {
        const int row = b0 + row0 + i;
        {
            float4 rv = *(const float4*)&g_relinit[row * D + c0];
            float2 p0 = unpack2(acc[i][0]);
            float2 p1 = unpack2(acc[i][1]);
            float4 o;
            o.x = fmaxf(p0.x + rv.x, 0.f);
            o.y = fmaxf(p0.y + rv.y, 0.f);
            o.z = fmaxf(p1.x + rv.z, 0.f);
            o.w = fmaxf(p1.y + rv.w, 0.f);
            *(float4*)&out[row * D + c0] = o;
        }
        {
            float4 rv = *(const float4*)&g_relinit[row * D + 128 + c0];
            float2 p0 = unpack2(acc[i][2]);
            float2 p1 = unpack2(acc[i][3]);
            float4 o;
            o.x = fmaxf(p0.x + rv.x, 0.f);
            o.y = fmaxf(p0.y + rv.y, 0.f);
            o.z = fmaxf(p1.x + rv.z, 0.f);
            o.w = fmaxf(p1.y + rv.w, 0.f);
            *(float4*)&out[row * D + 128 + c0] = o;
        }
    }
}

// ---------------- launch ----------------
extern "C" void kernel_launch(void* const* d_in, const int* in_sizes, int n_in,
                              void* d_out, int out_size) {
    (void)in_sizes; (void)n_in; (void)out_size;
    const int*   nbr  = (const int*)d_in[0];
    const int*   rel  = (const int*)d_in[1];
    const float* feat = (const float*)d_in[2];
    const float* W    = (const float*)d_in[3];
    const float* rw   = (const float*)d_in[4];
    float* out = (float*)d_out;

    const int rel_smem  = NREL * 129 * (int)sizeof(float);               // 122808 B
    const int main_smem = (BM * D + KC * D) * (int)sizeof(float) + 4096; // 102400 B
    cudaFuncSetAttribute(k_rel,  cudaFuncAttributeMaxDynamicSharedMemorySize, rel_smem);
    cudaFuncSetAttribute(k_main, cudaFuncAttributeMaxDynamicSharedMemorySize, main_smem);

    k_wt<<<256, 256>>>(W);
    k_rel<<<256, 256, rel_smem>>>(rel, rw);
    k_main<<<B_TOT / BM, NTHREADS, main_smem>>>(nbr, feat, out);
}

// round 5
// speedup vs baseline: 1.1984x; 1.1984x over previous
#include <cuda_runtime.h>
#include <cstdint>

#define B_TOT   32768
#define SAMP    16
#define D       256
#define NREL    238
#define BM      64
#define KC      32
#define NTHREADS 256

// ---------------- scratch (device globals: only legal scratch) ----------------
__device__ float g_Wt[D * D];             // Wt[d*256 + do] = W[do*256 + d]
__device__ float g_relinit[B_TOT * D];    // per-row relation means

// ---------------- packed fp32x2 helpers ----------------
__device__ __forceinline__ void fma2(unsigned long long& c, unsigned long long a,
                                     unsigned long long b) {
    asm("fma.rn.f32x2 %0, %1, %2, %0;" : "+l"(c) : "l"(a), "l"(b));
}
__device__ __forceinline__ unsigned long long splat2(float x) {
    unsigned long long r;
    asm("mov.b64 %0, {%1, %1};" : "=l"(r) : "f"(x));
    return r;
}
__device__ __forceinline__ float2 unpack2(unsigned long long v) {
    float2 f;
    asm("mov.b64 {%0, %1}, %2;" : "=f"(f.x), "=f"(f.y) : "l"(v));
    return f;
}

// ---------------- kernel 1: transpose weight [256,256] -> g_Wt ----------------
__global__ void k_wt(const float* __restrict__ W) {
    // 64 blocks x 256 threads, 4 elems/thread via float4 read
    int t = blockIdx.x * 256 + threadIdx.x;     // 16384 float4s
    float4 v = ((const float4*)W)[t];
    int dout = t >> 6;                          // row of W
    int d    = (t & 63) * 4;                    // col of W
    g_Wt[(d + 0) * D + dout] = v.x;
    g_Wt[(d + 1) * D + dout] = v.y;
    g_Wt[(d + 2) * D + dout] = v.z;
    g_Wt[(d + 3) * D + dout] = v.w;
}

// ---------------- kernel 2: relation means, relT resident in SMEM ----------------
// smem layout: [0, 8192) relation ids (2048 ints, 16B-aligned),
//              [8192, ...) sT[NREL][129] padded transpose (one 128-d half)
__global__ __launch_bounds__(256, 1) void k_rel(const int* __restrict__ rel,
                                                const float* __restrict__ rw) {
    extern __shared__ int smem_rel[];
    int*   sR = smem_rel;                       // 2048 ints = 8192 B
    float* sT = (float*)(smem_rel + 2048);      // [NREL][129]
    const int tid    = threadIdx.x;
    const int bstart = blockIdx.x * 128;        // grid = 256 blocks, 128 rows each

    // stage relation ids once (128 rows x 16 = 2048 ints = 512 int4)
    {
        const int4* src = (const int4*)(rel + bstart * SAMP);
        ((int4*)sR)[tid]       = src[tid];
        ((int4*)sR)[tid + 256] = src[tid + 256];
    }

    for (int p = 0; p < 2; ++p) {
        __syncthreads();                        // prior pass readers done / ids staged
        // stage relation_weight transposed for d in [128p, 128p+128)
        for (int idx = tid; idx < NREL * 128; idx += 256) {
            int dloc = idx / NREL;
            int r    = idx - dloc * NREL;
            sT[r * 129 + dloc] = rw[p * 128 * NREL + idx];
        }
        __syncthreads();

        const int d  = tid & 127;
        const int bh = tid >> 7;
        for (int k = 0; k < 64; ++k) {
            const int bloc = 2 * k + bh;        // warp-uniform
            const int* ids = sR + bloc * SAMP;
            float a0 = 0.f, a1 = 0.f;
            #pragma unroll
            for (int s = 0; s < 8; ++s) {
                a0 += sT[ids[2 * s] * 129 + d];
                a1 += sT[ids[2 * s + 1] * 129 + d];
            }
            g_relinit[(bstart + bloc) * D + p * 128 + d] = (a0 + a1) * (1.f / 16.f);
        }
    }
}

// ---------------- kernel 3: fused gather-mean + GEMM + rel-add + relu ----------------
__global__ __launch_bounds__(NTHREADS, 2) void k_main(const int* __restrict__ nbr,
                                                      const float* __restrict__ feat,
                                                      float* __restrict__ out) {
    extern __shared__ float smem[];
    float* sAgg = smem;                         // [64][256]  (65536 B)
    float* sW   = smem + BM * D;                // [KC][256]  (32768 B)
    int*   sIdx = (int*)(smem + BM * D + KC * D);  // 1024 ints (4096 B, 16B-aligned)

    const int tid = threadIdx.x;
    const int b0  = blockIdx.x * BM;

    // stage neighbor indices (contiguous 1024 ints)
    ((int4*)sIdx)[tid] = ((const int4*)(nbr + b0 * SAMP))[tid];
    __syncthreads();

    // ---------- Phase A: gather + mean into sAgg ----------
    {
        const int q  = tid & 63;                // float4 column within 256-dim row
        const int bg = tid >> 6;                // 0..3
        const float4* F4 = (const float4*)feat;
        #pragma unroll 2
        for (int k = 0; k < 16; ++k) {
            const int b = bg * 16 + k;          // warp-uniform b -> broadcast idx loads
            const int* ids = sIdx + b * SAMP;
            float4 acc = make_float4(0.f, 0.f, 0.f, 0.f);
            #pragma unroll
            for (int s = 0; s < SAMP; ++s) {
                int n = ids[s];
                float4 v = F4[n * 64 + q];      // warp reads 512B contiguous
                acc.x += v.x; acc.y += v.y; acc.z += v.z; acc.w += v.w;
            }
            const float inv = 1.f / 16.f;
            acc.x *= inv; acc.y *= inv; acc.z *= inv; acc.w *= inv;
            *(float4*)&sAgg[b * D + q * 4] = acc;
        }
    }
    __syncthreads();

    // ---------- Phase B: GEMM out[64][256] = sAgg @ W^T, packed f32x2 ----------
    // Scalar-a-per-k structure: ~85 live regs (acc 64 + b 8 + a/as 3 + addr),
    // safely under the 128-reg cap at 2 blocks/SM -> no spills.
    const int lane = tid & 31;
    const int warp = tid >> 5;
    const float* aRow = sAgg + warp * 8 * D;    // 8 rows per warp

    unsigned long long acc[8][4];               // 8 rows x 8 cols (4*lane.., 128+4*lane..)
    #pragma unroll
    for (int i = 0; i < 8; ++i)
        #pragma unroll
        for (int j = 0; j < 4; ++j) acc[i][j] = 0ull;

    for (int kc = 0; kc < D; kc += KC) {
        __syncthreads();
        // stage weight chunk: g_Wt rows [kc, kc+KC) are a contiguous 32KB block
        {
            const float4* src = (const float4*)(g_Wt + kc * D);
            float4* dst = (float4*)sW;
            #pragma unroll
            for (int i = 0; i < (KC * D / 4) / NTHREADS; ++i)   // 8 iters
                dst[tid + i * NTHREADS] = src[tid + i * NTHREADS];
        }
        __syncthreads();

        #pragma unroll 2
        for (int dd = 0; dd < KC; ++dd) {
            ulonglong2 blo = *(const ulonglong2*)&sW[dd * D + 4 * lane];
            ulonglong2 bhi = *(const ulonglong2*)&sW[dd * D + 128 + 4 * lane];
            #pragma unroll
            for (int i = 0; i < 8; ++i) {
                unsigned long long as = splat2(aRow[i * D + kc + dd]);
                fma2(acc[i][0], as, blo.x);
                fma2(acc[i][1], as, blo.y);
                fma2(acc[i][2], as, bhi.x);
                fma2(acc[i][3], as, bhi.y);
            }
        }
    }

    // ---------- Epilogue: + relation mean, relu, store ----------
    const int c0 = 4 * lane;
    #pragma unroll
    for (int i = 0; i < 8; ++i) {
        const int row = b0 + warp * 8 + i;
        {
            float4 rv = *(const float4*)&g_relinit[row * D + c0];
            float2 p0 = unpack2(acc[i][0]);
            float2 p1 = unpack2(acc[i][1]);
            float4 o;
            o.x = fmaxf(p0.x + rv.x, 0.f);
            o.y = fmaxf(p0.y + rv.y, 0.f);
            o.z = fmaxf(p1.x + rv.z, 0.f);
            o.w = fmaxf(p1.y + rv.w, 0.f);
            *(float4*)&out[row * D + c0] = o;
        }
        {
            float4 rv = *(const float4*)&g_relinit[row * D + 128 + c0];
            float2 p0 = unpack2(acc[i][2]);
            float2 p1 = unpack2(acc[i][3]);
            float4 o;
            o.x = fmaxf(p0.x + rv.x, 0.f);
            o.y = fmaxf(p0.y + rv.y, 0.f);
            o.z = fmaxf(p1.x + rv.z, 0.f);
            o.w = fmaxf(p1.y + rv.w, 0.f);
            *(float4*)&out[row * D + 128 + c0] = o;
        }
    }
}

// ---------------- launch ----------------
extern "C" void kernel_launch(void* const* d_in, const int* in_sizes, int n_in,
                              void* d_out, int out_size) {
    (void)in_sizes; (void)n_in; (void)out_size;
    const int*   nbr  = (const int*)d_in[0];
    const int*   rel  = (const int*)d_in[1];
    const float* feat = (const float*)d_in[2];
    const float* W    = (const float*)d_in[3];
    const float* rw   = (const float*)d_in[4];
    float* out = (float*)d_out;

    const int rel_smem  = 2048 * (int)sizeof(int) + NREL * 129 * (int)sizeof(float); // 131000 B
    const int main_smem = (BM * D + KC * D) * (int)sizeof(float) + 4096;             // 102400 B
    cudaFuncSetAttribute(k_rel,  cudaFuncAttributeMaxDynamicSharedMemorySize, rel_smem);
    cudaFuncSetAttribute(k_main, cudaFuncAttributeMaxDynamicSharedMemorySize, main_smem);

    k_wt<<<64, 256>>>(W);
    k_rel<<<256, 256, rel_smem>>>(rel, rw);
    k_main<<<B_TOT / BM, NTHREADS, main_smem>>>(nbr, feat, out);
}

// round 7
// speedup vs baseline: 1.3935x; 1.1628x over previous
#include <cuda_runtime.h>
#include <cuda_bf16.h>
#include <cstdint>

#define B_TOT   32768
#define SAMP    16
#define D       256
#define NREL    238
#define BM      64
#define NTHREADS 256

// ---------------- device-global scratch ----------------
__device__ __align__(16) unsigned char g_Whi[256 * 512];  // bf16 [dout][din] row-major
__device__ __align__(16) unsigned char g_Wlo[256 * 512];  // bf16 residual, same layout
__device__ float g_relinit[B_TOT * D];

// ---------------- smem layout for k_main (bytes) ----------------
#define A_PITCH  528            // 256 bf16 (512B) + 16B pad : 132 words % 32 = 4
#define B_PITCH  80             // 32 bf16 (64B) + 16B pad   : 20 words  % 32 = 20
#define SM_IDX   0              // 1024 ints = 4096 B
#define SM_AH    4096           // 64 * 528 = 33792
#define SM_AL    37888          // 33792
#define SM_BH    71680          // 256 * 80 = 20480
#define SM_BL    92160          // 20480
#define SM_TOTAL 112640

// ---------------- helpers ----------------
__device__ __forceinline__ uint32_t smem_u32(const void* p) {
    uint32_t a;
    asm("{ .reg .u64 t; cvta.to.shared.u64 t, %1; cvt.u32.u64 %0, t; }" : "=r"(a) : "l"(p));
    return a;
}
__device__ __forceinline__ void ldsm4(uint32_t& r0, uint32_t& r1, uint32_t& r2,
                                      uint32_t& r3, uint32_t addr) {
    asm volatile("ldmatrix.sync.aligned.m8n8.x4.shared.b16 {%0,%1,%2,%3}, [%4];"
                 : "=r"(r0), "=r"(r1), "=r"(r2), "=r"(r3) : "r"(addr));
}
__device__ __forceinline__ void mma_bf16(float* c, const uint32_t* a, const uint32_t* b) {
    asm volatile("mma.sync.aligned.m16n8k16.row.col.f32.bf16.bf16.f32 "
                 "{%0,%1,%2,%3}, {%4,%5,%6,%7}, {%8,%9}, {%0,%1,%2,%3};"
                 : "+f"(c[0]), "+f"(c[1]), "+f"(c[2]), "+f"(c[3])
                 : "r"(a[0]), "r"(a[1]), "r"(a[2]), "r"(a[3]), "r"(b[0]), "r"(b[1]));
}

// ---------------- kernel 1: weight -> bf16 hi/lo images [dout][din] ----------------
__global__ void k_wt(const float* __restrict__ W) {
    int t = blockIdx.x * 256 + threadIdx.x;     // 16384 float4s over [256][256]
    float4 v = ((const float4*)W)[t];
    int row  = t >> 6;
    int col4 = t & 63;

    __nv_bfloat162 h01 = __floats2bfloat162_rn(v.x, v.y);
    __nv_bfloat162 h23 = __floats2bfloat162_rn(v.z, v.w);
    float2 f01 = __bfloat1622float2(h01);
    float2 f23 = __bfloat1622float2(h23);
    __nv_bfloat162 l01 = __floats2bfloat162_rn(v.x - f01.x, v.y - f01.y);
    __nv_bfloat162 l23 = __floats2bfloat162_rn(v.z - f23.x, v.w - f23.y);

    *(uint2*)(g_Whi + row * 512 + col4 * 8) = make_uint2(*(uint32_t*)&h01, *(uint32_t*)&h23);
    *(uint2*)(g_Wlo + row * 512 + col4 * 8) = make_uint2(*(uint32_t*)&l01, *(uint32_t*)&l23);
}

// ---------------- kernel 2: relation means (unchanged, passing) ----------------
__global__ __launch_bounds__(256, 1) void k_rel(const int* __restrict__ rel,
                                                const float* __restrict__ rw) {
    extern __shared__ int smem_rel[];
    int*   sR = smem_rel;                       // 2048 ints
    float* sT = (float*)(smem_rel + 2048);      // [NREL][129]
    const int tid    = threadIdx.x;
    const int bstart = blockIdx.x * 128;

    {
        const int4* src = (const int4*)(rel + bstart * SAMP);
        ((int4*)sR)[tid]       = src[tid];
        ((int4*)sR)[tid + 256] = src[tid + 256];
    }
    for (int p = 0; p < 2; ++p) {
        __syncthreads();
        for (int idx = tid; idx < NREL * 128; idx += 256) {
            int dloc = idx / NREL;
            int r    = idx - dloc * NREL;
            sT[r * 129 + dloc] = rw[p * 128 * NREL + idx];
        }
        __syncthreads();
        const int d  = tid & 127;
        const int bh = tid >> 7;
        for (int k = 0; k < 64; ++k) {
            const int bloc = 2 * k + bh;
            const int* ids = sR + bloc * SAMP;
            float a0 = 0.f, a1 = 0.f;
            #pragma unroll
            for (int s = 0; s < 8; ++s) {
                a0 += sT[ids[2 * s] * 129 + d];
                a1 += sT[ids[2 * s + 1] * 129 + d];
            }
            g_relinit[(bstart + bloc) * D + p * 128 + d] = (a0 + a1) * (1.f / 16.f);
        }
    }
}

// ---------------- kernel 3: gather+mean -> split bf16 -> mma.sync GEMM -> epilogue ----
__global__ __launch_bounds__(NTHREADS, 2) void k_main(const int* __restrict__ nbr,
                                                      const float* __restrict__ feat,
                                                      float* __restrict__ out) {
    extern __shared__ char smem[];
    const uint32_t sbase = smem_u32(smem);
    const int tid = threadIdx.x;
    const int b0  = blockIdx.x * BM;

    // stage neighbor ids (1024 ints = 256 int4)
    ((int4*)(smem + SM_IDX))[tid] = ((const int4*)(nbr + b0 * SAMP))[tid];
    __syncthreads();

    // ---------- Phase A: gather + mean, split to bf16 hi/lo in smem ----------
    {
        const int q = tid & 63;                 // float4 column
        const int g = tid >> 6;                 // 0..3 row group (warp-uniform)
        const float4* F4 = (const float4*)feat;
        const int* sIdx = (const int*)(smem + SM_IDX);
        for (int k = 0; k < 16; ++k) {
            const int row = g * 16 + k;
            const int* ids = sIdx + row * SAMP;
            float4 a = make_float4(0.f, 0.f, 0.f, 0.f);
            #pragma unroll
            for (int s = 0; s < SAMP; ++s) {
                int n = ids[s];
                float4 v = F4[n * 64 + q];      // warp: 512B contiguous
                a.x += v.x; a.y += v.y; a.z += v.z; a.w += v.w;
            }
            const float inv = 1.f / 16.f;
            a.x *= inv; a.y *= inv; a.z *= inv; a.w *= inv;
            __nv_bfloat162 h01 = __floats2bfloat162_rn(a.x, a.y);
            __nv_bfloat162 h23 = __floats2bfloat162_rn(a.z, a.w);
            float2 f01 = __bfloat1622float2(h01);
            float2 f23 = __bfloat1622float2(h23);
            __nv_bfloat162 l01 = __floats2bfloat162_rn(a.x - f01.x, a.y - f01.y);
            __nv_bfloat162 l23 = __floats2bfloat162_rn(a.z - f23.x, a.w - f23.y);
            *(uint2*)(smem + SM_AH + row * A_PITCH + q * 8) =
                make_uint2(*(uint32_t*)&h01, *(uint32_t*)&h23);
            *(uint2*)(smem + SM_AL + row * A_PITCH + q * 8) =
                make_uint2(*(uint32_t*)&l01, *(uint32_t*)&l23);
        }
    }

    // ---------- Phase B: GEMM C[64][256] = A @ W^T via mma.sync bf16 3-pass ----------
    const int lane = tid & 31;
    const int warp = tid >> 5;
    const int mrow0 = (warp & 3) * 16;          // warp's 16 M rows
    const int ncol0 = (warp >> 2) * 128;        // warp's 128 N cols

    // ldmatrix lane->address maps (verified fragment layouts for m16n8k16)
    const uint32_t aBaseH = sbase + SM_AH + (mrow0 + (lane & 15)) * A_PITCH + ((lane >> 4) << 4);
    const uint32_t aBaseL = aBaseH + (SM_AL - SM_AH);
    const uint32_t bLane  = sbase + SM_BH
                          + (uint32_t)(ncol0 + ((lane >> 4) << 3) + (lane & 7)) * B_PITCH
                          + (((lane >> 3) & 1) << 4);

    float c[16][4];
    #pragma unroll
    for (int i = 0; i < 16; ++i)
        #pragma unroll
        for (int j = 0; j < 4; ++j) c[i][j] = 0.f;

    for (int kc = 0; kc < 8; ++kc) {            // K chunks of 32
        __syncthreads();                        // prev chunk fully consumed
        // stage W chunk hi+lo: 256 rows x 64B (4 x uint4 per row)
        {
            #pragma unroll
            for (int i = 0; i < 4; ++i) {
                int idx = tid + i * NTHREADS;   // 0..1023
                int row = idx >> 2;
                int seg = idx & 3;
                *(uint4*)(smem + SM_BH + row * B_PITCH + seg * 16) =
                    *(const uint4*)(g_Whi + row * 512 + kc * 64 + seg * 16);
                *(uint4*)(smem + SM_BL + row * B_PITCH + seg * 16) =
                    *(const uint4*)(g_Wlo + row * 512 + kc * 64 + seg * 16);
            }
        }
        __syncthreads();

        #pragma unroll
        for (int ks = 0; ks < 2; ++ks) {        // two k16 steps per chunk
            const uint32_t ka = kc * 64 + ks * 32;   // byte offset into A row
            const uint32_t kb = ks * 32;             // byte offset into B row
            uint32_t aH[4], aL[4];
            ldsm4(aH[0], aH[1], aH[2], aH[3], aBaseH + ka);
            ldsm4(aL[0], aL[1], aL[2], aL[3], aBaseL + ka);
            #pragma unroll
            for (int p = 0; p < 8; ++p) {       // 8 n-tile pairs (16 cols each)
                uint32_t bh[4], bl[4];
                const uint32_t bo = bLane + (uint32_t)(p * 16) * B_PITCH + kb;
                ldsm4(bh[0], bh[1], bh[2], bh[3], bo);
                ldsm4(bl[0], bl[1], bl[2], bl[3], bo + (SM_BL - SM_BH));
                mma_bf16(c[2 * p],     aH, bh);     // Ah*Bh
                mma_bf16(c[2 * p + 1], aH, bh + 2);
                mma_bf16(c[2 * p],     aH, bl);     // Ah*Bl
                mma_bf16(c[2 * p + 1], aH, bl + 2);
                mma_bf16(c[2 * p],     aL, bh);     // Al*Bh
                mma_bf16(c[2 * p + 1], aL, bh + 2);
            }
        }
    }

    // ---------- Epilogue: + relation mean, relu, store ----------
    {
        const int tig = lane & 3;
        const int gid = lane >> 2;
        const int r0 = b0 + mrow0 + gid;
        const int r1 = r0 + 8;
        #pragma unroll
        for (int nt = 0; nt < 16; ++nt) {
            const int col = ncol0 + nt * 8 + tig * 2;
            float2 rv0 = *(const float2*)&g_relinit[r0 * D + col];
            float2 rv1 = *(const float2*)&g_relinit[r1 * D + col];
            float2 o0, o1;
            o0.x = fmaxf(c[nt][0] + rv0.x, 0.f);
            o0.y = fmaxf(c[nt][1] + rv0.y, 0.f);
            o1.x = fmaxf(c[nt][2] + rv1.x, 0.f);
            o1.y = fmaxf(c[nt][3] + rv1.y, 0.f);
            *(float2*)&out[r0 * D + col] = o0;
            *(float2*)&out[r1 * D + col] = o1;
        }
    }
}

// ---------------- launch ----------------
extern "C" void kernel_launch(void* const* d_in, const int* in_sizes, int n_in,
                              void* d_out, int out_size) {
    (void)in_sizes; (void)n_in; (void)out_size;
    const int*   nbr  = (const int*)d_in[0];
    const int*   rel  = (const int*)d_in[1];
    const float* feat = (const float*)d_in[2];
    const float* W    = (const float*)d_in[3];
    const float* rw   = (const float*)d_in[4];
    float* out = (float*)d_out;

    const int rel_smem = 2048 * (int)sizeof(int) + NREL * 129 * (int)sizeof(float);
    cudaFuncSetAttribute(k_rel,  cudaFuncAttributeMaxDynamicSharedMemorySize, rel_smem);
    cudaFuncSetAttribute(k_main, cudaFuncAttributeMaxDynamicSharedMemorySize, SM_TOTAL);

    k_wt<<<64, 256>>>(W);
    k_rel<<<256, 256, rel_smem>>>(rel, rw);
    k_main<<<B_TOT / BM, NTHREADS, SM_TOTAL>>>(nbr, feat, out);
}

// round 8
// speedup vs baseline: 1.9349x; 1.3886x over previous
#include <cuda_runtime.h>
#include <cuda_bf16.h>
#include <cstdint>

#define B_TOT   32768
#define SAMP    16
#define D       256
#define NREL    238
#define BM      64
#define NTHREADS 256

// ---------------- device-global scratch ----------------
// W packed in m16n8k16 B-fragment order: index g = i*1024 + j*32 + lane
// (i = k16 step 0..15, j = 8-col n-tile 0..31), regs r=0,1 at [2g+r].
__device__ __align__(16) uint32_t g_Bfh[32768];   // bf16x2 hi
__device__ __align__(16) uint32_t g_Bfl[32768];   // bf16x2 residual
__device__ float g_relinit[B_TOT * D];

// ---------------- smem layout for k_main (bytes) ----------------
#define A_PITCH  528            // 256 bf16 (512B) + 16B pad (conflict-free, proven R7)
#define SM_IDX   0              // 1024 ints = 4096
#define SM_AH    4096           // 64 * 528 = 33792
#define SM_AL    37888          // 33792
#define SM_TOTAL 71680

// ---------------- helpers ----------------
__device__ __forceinline__ uint32_t smem_u32(const void* p) {
    uint32_t a;
    asm("{ .reg .u64 t; cvta.to.shared.u64 t, %1; cvt.u32.u64 %0, t; }" : "=r"(a) : "l"(p));
    return a;
}
__device__ __forceinline__ void ldsm4(uint32_t& r0, uint32_t& r1, uint32_t& r2,
                                      uint32_t& r3, uint32_t addr) {
    asm volatile("ldmatrix.sync.aligned.m8n8.x4.shared.b16 {%0,%1,%2,%3}, [%4];"
                 : "=r"(r0), "=r"(r1), "=r"(r2), "=r"(r3) : "r"(addr));
}
__device__ __forceinline__ void mma_bf16(float* c, const uint32_t* a, const uint32_t* b) {
    asm volatile("mma.sync.aligned.m16n8k16.row.col.f32.bf16.bf16.f32 "
                 "{%0,%1,%2,%3}, {%4,%5,%6,%7}, {%8,%9}, {%0,%1,%2,%3};"
                 : "+f"(c[0]), "+f"(c[1]), "+f"(c[2]), "+f"(c[3])
                 : "r"(a[0]), "r"(a[1]), "r"(a[2]), "r"(a[3]), "r"(b[0]), "r"(b[1]));
}

// ---------------- kernel 1: rel means + (blocks 0-63) W fragment packing ----------------
__global__ __launch_bounds__(256, 1) void k_prep(const int* __restrict__ rel,
                                                 const float* __restrict__ rw,
                                                 const float* __restrict__ W) {
    extern __shared__ int smem_rel[];
    int*   sR = smem_rel;                       // 2048 ints (16B-aligned)
    float* sT = (float*)(smem_rel + 2048);      // [NREL][129]
    const int tid = threadIdx.x;
    const int bx  = blockIdx.x;

    // ---- W -> bf16 hi/lo fragment images (global-only work, no smem) ----
    if (bx < 64) {
        const int g = bx * 256 + tid;           // 0..16383
        const int l = g & 31;
        const int j = (g >> 5) & 31;
        const int i = g >> 10;
        const int n  = j * 8 + (l >> 2);        // output col (W row)
        const int k0 = i * 16 + (l & 3) * 2;    // k within step
        #pragma unroll
        for (int r = 0; r < 2; ++r) {
            const int k = k0 + r * 8;
            const float w0 = W[n * 256 + k];
            const float w1 = W[n * 256 + k + 1];
            __nv_bfloat162 h = __floats2bfloat162_rn(w0, w1);
            float2 f = __bfloat1622float2(h);
            __nv_bfloat162 lo = __floats2bfloat162_rn(w0 - f.x, w1 - f.y);
            g_Bfh[2 * g + r] = *(uint32_t*)&h;
            g_Bfl[2 * g + r] = *(uint32_t*)&lo;
        }
    }

    // ---- relation means (proven R7 code) ----
    const int bstart = bx * 128;
    {
        const int4* src = (const int4*)(rel + bstart * SAMP);
        ((int4*)sR)[tid]       = src[tid];
        ((int4*)sR)[tid + 256] = src[tid + 256];
    }
    for (int p = 0; p < 2; ++p) {
        __syncthreads();
        for (int idx = tid; idx < NREL * 128; idx += 256) {
            int dloc = idx / NREL;
            int r    = idx - dloc * NREL;
            sT[r * 129 + dloc] = rw[p * 128 * NREL + idx];
        }
        __syncthreads();
        const int d  = tid & 127;
        const int bh = tid >> 7;
        for (int k = 0; k < 64; ++k) {
            const int bloc = 2 * k + bh;
            const int* ids = sR + bloc * SAMP;
            float a0 = 0.f, a1 = 0.f;
            #pragma unroll
            for (int s = 0; s < 8; ++s) {
                a0 += sT[ids[2 * s] * 129 + d];
                a1 += sT[ids[2 * s + 1] * 129 + d];
            }
            g_relinit[(bstart + bloc) * D + p * 128 + d] = (a0 + a1) * (1.f / 16.f);
        }
    }
}

// ---------------- kernel 2: gather+mean -> split bf16 -> mma.sync (B via LDG) ----------
__global__ __launch_bounds__(NTHREADS, 2) void k_main(const int* __restrict__ nbr,
                                                      const float* __restrict__ feat,
                                                      float* __restrict__ out) {
    extern __shared__ char smem[];
    const uint32_t sbase = smem_u32(smem);
    const int tid = threadIdx.x;
    const int b0  = blockIdx.x * BM;

    // stage neighbor ids (1024 ints = 256 int4)
    ((int4*)(smem + SM_IDX))[tid] = ((const int4*)(nbr + b0 * SAMP))[tid];
    __syncthreads();

    // ---------- Phase A: gather + mean, split to bf16 hi/lo in smem ----------
    {
        const int q = tid & 63;                 // float4 column
        const int g = tid >> 6;                 // 0..3 row group (warp-uniform)
        const float4* F4 = (const float4*)feat;
        const int* sIdx = (const int*)(smem + SM_IDX);
        #pragma unroll 2
        for (int k = 0; k < 16; ++k) {
            const int row = g * 16 + k;
            const int* ids = sIdx + row * SAMP;
            float4 a = make_float4(0.f, 0.f, 0.f, 0.f);
            #pragma unroll
            for (int s = 0; s < SAMP; ++s) {
                int n = ids[s];
                float4 v = F4[n * 64 + q];      // warp: 512B contiguous
                a.x += v.x; a.y += v.y; a.z += v.z; a.w += v.w;
            }
            const float inv = 1.f / 16.f;
            a.x *= inv; a.y *= inv; a.z *= inv; a.w *= inv;
            __nv_bfloat162 h01 = __floats2bfloat162_rn(a.x, a.y);
            __nv_bfloat162 h23 = __floats2bfloat162_rn(a.z, a.w);
            float2 f01 = __bfloat1622float2(h01);
            float2 f23 = __bfloat1622float2(h23);
            __nv_bfloat162 l01 = __floats2bfloat162_rn(a.x - f01.x, a.y - f01.y);
            __nv_bfloat162 l23 = __floats2bfloat162_rn(a.z - f23.x, a.w - f23.y);
            *(uint2*)(smem + SM_AH + row * A_PITCH + q * 8) =
                make_uint2(*(uint32_t*)&h01, *(uint32_t*)&h23);
            *(uint2*)(smem + SM_AL + row * A_PITCH + q * 8) =
                make_uint2(*(uint32_t*)&l01, *(uint32_t*)&l23);
        }
    }
    __syncthreads();                            // last sync until exit

    // ---------- Phase B: warp tile M64xN32, B fragments streamed via LDG.64 ----------
    const int lane = tid & 31;
    const int warp = tid >> 5;
    const int j0   = warp * 4;                  // 4 distinct 8-col n-tiles per warp

    // A ldsm base (proven R7 map): rows (lane&15), +16B half by lane>>4
    const uint32_t aAddrH = sbase + SM_AH + (uint32_t)(lane & 15) * A_PITCH + ((lane >> 4) << 4);
    const uint32_t aAddrL = aAddrH + (SM_AL - SM_AH);

    float c[4][4][4];                           // [mt][nt][frag]
    #pragma unroll
    for (int mt = 0; mt < 4; ++mt)
        #pragma unroll
        for (int nt = 0; nt < 4; ++nt)
            #pragma unroll
            for (int r = 0; r < 4; ++r) c[mt][nt][r] = 0.f;

    // double-buffered B fragments in registers
    uint2 bh[2][4], bl[2][4];
    {
        const uint32_t base = (uint32_t)(j0 * 32 + lane) * 2;
        #pragma unroll
        for (int nt = 0; nt < 4; ++nt) {
            bh[0][nt] = *(const uint2*)(g_Bfh + base + nt * 64);
            bl[0][nt] = *(const uint2*)(g_Bfl + base + nt * 64);
        }
    }

    #pragma unroll 2
    for (int i = 0; i < 16; ++i) {
        const int cur = i & 1, nxt = cur ^ 1;
        if (i < 15) {
            const uint32_t base = (uint32_t)((i + 1) * 1024 + j0 * 32 + lane) * 2;
            #pragma unroll
            for (int nt = 0; nt < 4; ++nt) {
                bh[nxt][nt] = *(const uint2*)(g_Bfh + base + nt * 64);
                bl[nxt][nt] = *(const uint2*)(g_Bfl + base + nt * 64);
            }
        }
        #pragma unroll
        for (int mt = 0; mt < 4; ++mt) {
            uint32_t aH[4], aL[4];
            const uint32_t ao = (uint32_t)(mt * 16) * A_PITCH + (uint32_t)(i * 32);
            ldsm4(aH[0], aH[1], aH[2], aH[3], aAddrH + ao);
            ldsm4(aL[0], aL[1], aL[2], aL[3], aAddrL + ao);
            #pragma unroll
            for (int nt = 0; nt < 4; ++nt) {
                mma_bf16(c[mt][nt], aH, (const uint32_t*)&bh[cur][nt]);  // Ah*Bh
                mma_bf16(c[mt][nt], aH, (const uint32_t*)&bl[cur][nt]);  // Ah*Bl
                mma_bf16(c[mt][nt], aL, (const uint32_t*)&bh[cur][nt]);  // Al*Bh
            }
        }
    }

    // ---------- Epilogue: + relation mean, relu, store ----------
    {
        const int colb = warp * 32 + (lane & 3) * 2;
        const int rowb = b0 + (lane >> 2);
        #pragma unroll
        for (int mt = 0; mt < 4; ++mt) {
            const int r0 = rowb + mt * 16;
            const int r1 = r0 + 8;
            #pragma unroll
            for (int nt = 0; nt < 4; ++nt) {
                const int col = colb + nt * 8;
                float2 rv0 = *(const float2*)&g_relinit[r0 * D + col];
                float2 rv1 = *(const float2*)&g_relinit[r1 * D + col];
                float2 o0, o1;
                o0.x = fmaxf(c[mt][nt][0] + rv0.x, 0.f);
                o0.y = fmaxf(c[mt][nt][1] + rv0.y, 0.f);
                o1.x = fmaxf(c[mt][nt][2] + rv1.x, 0.f);
                o1.y = fmaxf(c[mt][nt][3] + rv1.y, 0.f);
                *(float2*)&out[r0 * D + col] = o0;
                *(float2*)&out[r1 * D + col] = o1;
            }
        }
    }
}

// ---------------- launch ----------------
extern "C" void kernel_launch(void* const* d_in, const int* in_sizes, int n_in,
                              void* d_out, int out_size) {
    (void)in_sizes; (void)n_in; (void)out_size;
    const int*   nbr  = (const int*)d_in[0];
    const int*   rel  = (const int*)d_in[1];
    const float* feat = (const float*)d_in[2];
    const float* W    = (const float*)d_in[3];
    const float* rw   = (const float*)d_in[4];
    float* out = (float*)d_out;

    const int rel_smem = 2048 * (int)sizeof(int) + NREL * 129 * (int)sizeof(float);
    cudaFuncSetAttribute(k_prep, cudaFuncAttributeMaxDynamicSharedMemorySize, rel_smem);
    cudaFuncSetAttribute(k_main, cudaFuncAttributeMaxDynamicSharedMemorySize, SM_TOTAL);

    k_prep<<<256, 256, rel_smem>>>(rel, rw, W);
    k_main<<<B_TOT / BM, NTHREADS, SM_TOTAL>>>(nbr, feat, out);
}

// round 9
// speedup vs baseline: 2.7202x; 1.4059x over previous
#include <cuda_runtime.h>
#include <cuda_bf16.h>
#include <cstdint>

#define B_TOT   32768
#define SAMP    16
#define D       256
#define NREL    238
#define BM      64
#define NTHREADS 256

// ---------------- device-global scratch ----------------
// W packed in m16n8k16 B-fragment order: index g = i*1024 + j*32 + lane
__device__ __align__(16) uint32_t g_Bfh[32768];   // bf16x2 hi
__device__ __align__(16) uint32_t g_Bfl[32768];   // bf16x2 residual
__device__ __align__(16) float g_rwT[NREL * D];   // relation_weight transposed [r][d]
__device__ float g_relinit[B_TOT * D];

// ---------------- smem layout for k_main (bytes) ----------------
#define A_PITCH  528
#define SM_IDX   0
#define SM_AH    4096
#define SM_AL    37888
#define SM_TOTAL 71680

// ---------------- helpers ----------------
__device__ __forceinline__ uint32_t smem_u32(const void* p) {
    uint32_t a;
    asm("{ .reg .u64 t; cvta.to.shared.u64 t, %1; cvt.u32.u64 %0, t; }" : "=r"(a) : "l"(p));
    return a;
}
__device__ __forceinline__ void ldsm4(uint32_t& r0, uint32_t& r1, uint32_t& r2,
                                      uint32_t& r3, uint32_t addr) {
    asm volatile("ldmatrix.sync.aligned.m8n8.x4.shared.b16 {%0,%1,%2,%3}, [%4];"
                 : "=r"(r0), "=r"(r1), "=r"(r2), "=r"(r3) : "r"(addr));
}
__device__ __forceinline__ void mma_bf16(float* c, const uint32_t* a, const uint32_t* b) {
    asm volatile("mma.sync.aligned.m16n8k16.row.col.f32.bf16.bf16.f32 "
                 "{%0,%1,%2,%3}, {%4,%5,%6,%7}, {%8,%9}, {%0,%1,%2,%3};"
                 : "+f"(c[0]), "+f"(c[1]), "+f"(c[2]), "+f"(c[3])
                 : "r"(a[0]), "r"(a[1]), "r"(a[2]), "r"(a[3]), "r"(b[0]), "r"(b[1]));
}

// ---------------- kernel 0: transpose rw + pack W fragments ----------------
// grid = 238 blocks x 256 threads. Block bx transposes relation row bx;
// blocks 0..63 additionally pack W into mma B-fragment images.
__global__ void k_prep0(const float* __restrict__ rw, const float* __restrict__ W) {
    const int tid = threadIdx.x;
    const int bx  = blockIdx.x;

    // transpose: rwT[bx][d] = rw[d][bx]
    g_rwT[bx * D + tid] = rw[tid * NREL + bx];

    // W -> bf16 hi/lo fragment images (proven R8 math)
    if (bx < 64) {
        const int g = bx * 256 + tid;           // 0..16383
        const int l = g & 31;
        const int j = (g >> 5) & 31;
        const int i = g >> 10;
        const int n  = j * 8 + (l >> 2);
        const int k0 = i * 16 + (l & 3) * 2;
        #pragma unroll
        for (int r = 0; r < 2; ++r) {
            const int k = k0 + r * 8;
            const float w0 = W[n * 256 + k];
            const float w1 = W[n * 256 + k + 1];
            __nv_bfloat162 h = __floats2bfloat162_rn(w0, w1);
            float2 f = __bfloat1622float2(h);
            __nv_bfloat162 lo = __floats2bfloat162_rn(w0 - f.x, w1 - f.y);
            g_Bfh[2 * g + r] = *(uint32_t*)&h;
            g_Bfl[2 * g + r] = *(uint32_t*)&lo;
        }
    }
}

// ---------------- kernel 1: relation means via L1-resident gather ----------------
// No smem, no barriers, full occupancy. Warp handles 8 rows; each lane covers
// d = 4*lane..4*lane+3 and d+128.. via two LDG.128 per sample (512B/warp, L1-hot).
__global__ __launch_bounds__(256, 6) void k_rel(const int* __restrict__ rel) {
    const int lane = threadIdx.x & 31;
    const int warp = threadIdx.x >> 5;
    const int row0 = blockIdx.x * 64 + warp * 8;
    const float4* T4 = (const float4*)g_rwT;    // [238][64] float4

    for (int i = 0; i < 8; ++i) {
        const int row = row0 + i;
        const int* ids = rel + row * SAMP;
        float4 lo = make_float4(0.f, 0.f, 0.f, 0.f);
        float4 hi = make_float4(0.f, 0.f, 0.f, 0.f);
        #pragma unroll
        for (int s = 0; s < SAMP; ++s) {
            const int r = __ldg(ids + s);       // warp-uniform -> broadcast
            float4 vl = __ldg(&T4[r * 64 + lane]);
            float4 vh = __ldg(&T4[r * 64 + 32 + lane]);
            lo.x += vl.x; lo.y += vl.y; lo.z += vl.z; lo.w += vl.w;
            hi.x += vh.x; hi.y += vh.y; hi.z += vh.z; hi.w += vh.w;
        }
        const float inv = 1.f / 16.f;
        lo.x *= inv; lo.y *= inv; lo.z *= inv; lo.w *= inv;
        hi.x *= inv; hi.y *= inv; hi.z *= inv; hi.w *= inv;
        *(float4*)&g_relinit[row * D + lane * 4]       = lo;
        *(float4*)&g_relinit[row * D + 128 + lane * 4] = hi;
    }
}

// ---------------- kernel 2: gather+mean -> split bf16 -> mma.sync (UNCHANGED R8) ----
__global__ __launch_bounds__(NTHREADS, 2) void k_main(const int* __restrict__ nbr,
                                                      const float* __restrict__ feat,
                                                      float* __restrict__ out) {
    extern __shared__ char smem[];
    const uint32_t sbase = smem_u32(smem);
    const int tid = threadIdx.x;
    const int b0  = blockIdx.x * BM;

    ((int4*)(smem + SM_IDX))[tid] = ((const int4*)(nbr + b0 * SAMP))[tid];
    __syncthreads();

    // ---------- Phase A: gather + mean, split to bf16 hi/lo in smem ----------
    {
        const int q = tid & 63;
        const int g = tid >> 6;
        const float4* F4 = (const float4*)feat;
        const int* sIdx = (const int*)(smem + SM_IDX);
        #pragma unroll 2
        for (int k = 0; k < 16; ++k) {
            const int row = g * 16 + k;
            const int* ids = sIdx + row * SAMP;
            float4 a = make_float4(0.f, 0.f, 0.f, 0.f);
            #pragma unroll
            for (int s = 0; s < SAMP; ++s) {
                int n = ids[s];
                float4 v = F4[n * 64 + q];
                a.x += v.x; a.y += v.y; a.z += v.z; a.w += v.w;
            }
            const float inv = 1.f / 16.f;
            a.x *= inv; a.y *= inv; a.z *= inv; a.w *= inv;
            __nv_bfloat162 h01 = __floats2bfloat162_rn(a.x, a.y);
            __nv_bfloat162 h23 = __floats2bfloat162_rn(a.z, a.w);
            float2 f01 = __bfloat1622float2(h01);
            float2 f23 = __bfloat1622float2(h23);
            __nv_bfloat162 l01 = __floats2bfloat162_rn(a.x - f01.x, a.y - f01.y);
            __nv_bfloat162 l23 = __floats2bfloat162_rn(a.z - f23.x, a.w - f23.y);
            *(uint2*)(smem + SM_AH + row * A_PITCH + q * 8) =
                make_uint2(*(uint32_t*)&h01, *(uint32_t*)&h23);
            *(uint2*)(smem + SM_AL + row * A_PITCH + q * 8) =
                make_uint2(*(uint32_t*)&l01, *(uint32_t*)&l23);
        }
    }
    __syncthreads();

    // ---------- Phase B: warp tile M64xN32, B fragments via LDG.64 ----------
    const int lane = tid & 31;
    const int warp = tid >> 5;
    const int j0   = warp * 4;

    const uint32_t aAddrH = sbase + SM_AH + (uint32_t)(lane & 15) * A_PITCH + ((lane >> 4) << 4);
    const uint32_t aAddrL = aAddrH + (SM_AL - SM_AH);

    float c[4][4][4];
    #pragma unroll
    for (int mt = 0; mt < 4; ++mt)
        #pragma unroll
        for (int nt = 0; nt < 4; ++nt)
            #pragma unroll
            for (int r = 0; r < 4; ++r) c[mt][nt][r] = 0.f;

    uint2 bh[2][4], bl[2][4];
    {
        const uint32_t base = (uint32_t)(j0 * 32 + lane) * 2;
        #pragma unroll
        for (int nt = 0; nt < 4; ++nt) {
            bh[0][nt] = *(const uint2*)(g_Bfh + base + nt * 64);
            bl[0][nt] = *(const uint2*)(g_Bfl + base + nt * 64);
        }
    }

    #pragma unroll 2
    for (int i = 0; i < 16; ++i) {
        const int cur = i & 1, nxt = cur ^ 1;
        if (i < 15) {
            const uint32_t base = (uint32_t)((i + 1) * 1024 + j0 * 32 + lane) * 2;
            #pragma unroll
            for (int nt = 0; nt < 4; ++nt) {
                bh[nxt][nt] = *(const uint2*)(g_Bfh + base + nt * 64);
                bl[nxt][nt] = *(const uint2*)(g_Bfl + base + nt * 64);
            }
        }
        #pragma unroll
        for (int mt = 0; mt < 4; ++mt) {
            uint32_t aH[4], aL[4];
            const uint32_t ao = (uint32_t)(mt * 16) * A_PITCH + (uint32_t)(i * 32);
            ldsm4(aH[0], aH[1], aH[2], aH[3], aAddrH + ao);
            ldsm4(aL[0], aL[1], aL[2], aL[3], aAddrL + ao);
            #pragma unroll
            for (int nt = 0; nt < 4; ++nt) {
                mma_bf16(c[mt][nt], aH, (const uint32_t*)&bh[cur][nt]);
                mma_bf16(c[mt][nt], aH, (const uint32_t*)&bl[cur][nt]);
                mma_bf16(c[mt][nt], aL, (const uint32_t*)&bh[cur][nt]);
            }
        }
    }

    // ---------- Epilogue: + relation mean, relu, store ----------
    {
        const int colb = warp * 32 + (lane & 3) * 2;
        const int rowb = b0 + (lane >> 2);
        #pragma unroll
        for (int mt = 0; mt < 4; ++mt) {
            const int r0 = rowb + mt * 16;
            const int r1 = r0 + 8;
            #pragma unroll
            for (int nt = 0; nt < 4; ++nt) {
                const int col = colb + nt * 8;
                float2 rv0 = *(const float2*)&g_relinit[r0 * D + col];
                float2 rv1 = *(const float2*)&g_relinit[r1 * D + col];
                float2 o0, o1;
                o0.x = fmaxf(c[mt][nt][0] + rv0.x, 0.f);
                o0.y = fmaxf(c[mt][nt][1] + rv0.y, 0.f);
                o1.x = fmaxf(c[mt][nt][2] + rv1.x, 0.f);
                o1.y = fmaxf(c[mt][nt][3] + rv1.y, 0.f);
                *(float2*)&out[r0 * D + col] = o0;
                *(float2*)&out[r1 * D + col] = o1;
            }
        }
    }
}

// ---------------- launch ----------------
extern "C" void kernel_launch(void* const* d_in, const int* in_sizes, int n_in,
                              void* d_out, int out_size) {
    (void)in_sizes; (void)n_in; (void)out_size;
    const int*   nbr  = (const int*)d_in[0];
    const int*   rel  = (const int*)d_in[1];
    const float* feat = (const float*)d_in[2];
    const float* W    = (const float*)d_in[3];
    const float* rw   = (const float*)d_in[4];
    float* out = (float*)d_out;

    cudaFuncSetAttribute(k_main, cudaFuncAttributeMaxDynamicSharedMemorySize, SM_TOTAL);

    k_prep0<<<NREL, 256>>>(rw, W);
    k_rel<<<B_TOT / 64, 256>>>(rel);
    k_main<<<B_TOT / BM, NTHREADS, SM_TOTAL>>>(nbr, feat, out);
}